// round 1
// baseline (speedup 1.0000x reference)
#include <cuda_runtime.h>
#include <math.h>
#include <stdint.h>

// ---------------- problem constants ----------------
#define BATCH   64
#define SEQ     200
#define EMBED   64
#define VOCAB   95
#define LOUT    96          // (200-9)/2+1
#define NCAPS   50
#define CAPSD   8
#define ODIM    16
#define NROUTE  3072        // 32 * LOUT
#define HID1    512
#define HID2    1024
#define NOUT    19000       // SEQ*VOCAB
#define CO      (NCAPS*ODIM)   // 800

// ---------------- device scratch (static = allowed) ----------------
__device__ float g_u[BATCH * NROUTE * CAPSD];                  // 6.3 MB
__device__ float g_uhat[(size_t)BATCH * NROUTE * NCAPS * ODIM]; // 629 MB
__device__ float g_S[BATCH * CO];      // s accumulator (reused each pass)
__device__ float g_vsum[BATCH * CO];   // v0, then v0+v1
__device__ float g_vtop[BATCH * ODIM];
__device__ int   g_amax[BATCH];
__device__ float g_h1[BATCH * HID1];
__device__ float g_h2[BATCH * HID2];

// ---------------- kernel 1: embedding + conv1d + relu -> u ----------------
// grid (2, BATCH): x = l-half (48 outputs), y = b. 256 threads = 256 out channels.
__global__ __launch_bounds__(256) void conv_embed_kernel(
    const int* __restrict__ x, const float* __restrict__ emb,
    const float* __restrict__ cw, const float* __restrict__ cb)
{
    __shared__ int   xs[104];
    __shared__ float se[104 * EMBED];   // embedded window [s_local][ic]

    const int l0 = blockIdx.x * 48;
    const int b  = blockIdx.y;
    const int t  = threadIdx.x;

    for (int f = t; f < 104; f += 256) xs[f] = x[b * SEQ + 2 * l0 + f];
    __syncthreads();
    for (int f = t; f < 104 * EMBED; f += 256) {
        int s = f >> 6, ic = f & 63;
        se[f] = emb[xs[s] * EMBED + ic];
    }
    __syncthreads();

    const int ch = t;
    float acc[48];
    {
        float bias = cb[ch];
        #pragma unroll
        for (int j = 0; j < 48; j++) acc[j] = bias;
    }

    const float* cwr = cw + (size_t)ch * (EMBED * 9);
    for (int ic = 0; ic < EMBED; ic++) {
        float w_r[9];
        #pragma unroll
        for (int k = 0; k < 9; k++) w_r[k] = __ldg(cwr + ic * 9 + k);
        #pragma unroll
        for (int lt = 0; lt < 6; lt++) {
            float se_r[23];
            #pragma unroll
            for (int q = 0; q < 23; q++) se_r[q] = se[(lt * 16 + q) * EMBED + ic];
            #pragma unroll
            for (int j = 0; j < 8; j++) {
                float a = acc[lt * 8 + j];
                #pragma unroll
                for (int k = 0; k < 9; k++) a = fmaf(se_r[2 * j + k], w_r[k], a);
                acc[lt * 8 + j] = a;
            }
        }
    }

    const int g = ch >> 3, i = ch & 7;
    #pragma unroll
    for (int j = 0; j < 48; j++) {
        int l = l0 + j;
        float v = acc[j];
        v = v > 0.f ? v : 0.f;
        g_u[((size_t)(b * NROUTE) + g * LOUT + l) * CAPSD + i] = v;
    }
}

// ---------------- zero g_S ----------------
__global__ void zero_S_kernel() {
    int i = blockIdx.x * blockDim.x + threadIdx.x;
    if (i < BATCH * CO) g_S[i] = 0.f;
}

// ---------------- kernel 2: u_hat generation + fused S0 (= sum_r u_hat) ----
// grid (96, 50): x = r-tile (32 routes), y = c. 256 threads.
// thread: r = t&31 (lane), bg = t>>5 (warp). Each thread: 8 batches x 16 o.
__global__ __launch_bounds__(256) void gen_uhat_kernel(const float* __restrict__ W)
{
    __shared__ float Ws[128 * 33];   // [i*16+o][r], padded

    const int r0 = blockIdx.x * 32;
    const int c  = blockIdx.y;
    const int t  = threadIdx.x;

    for (int f = t; f < 32 * 128; f += 256) {
        int rl = f >> 7, io = f & 127;
        Ws[io * 33 + rl] = W[(size_t)(c * NROUTE + r0 + rl) * 128 + io];
    }
    __syncthreads();

    const int r  = t & 31;
    const int bg = t >> 5;
    const int rg = r0 + r;

    float u_r[8][8];
    #pragma unroll
    for (int b8 = 0; b8 < 8; b8++) {
        const float4* up = reinterpret_cast<const float4*>(
            g_u + ((size_t)((bg * 8 + b8) * NROUTE + rg)) * CAPSD);
        float4 a = up[0], q = up[1];
        u_r[b8][0] = a.x; u_r[b8][1] = a.y; u_r[b8][2] = a.z; u_r[b8][3] = a.w;
        u_r[b8][4] = q.x; u_r[b8][5] = q.y; u_r[b8][6] = q.z; u_r[b8][7] = q.w;
    }

    #pragma unroll
    for (int oh = 0; oh < 2; oh++) {
        float acc[8][8];   // [o8][b8]
        #pragma unroll
        for (int o8 = 0; o8 < 8; o8++)
            #pragma unroll
            for (int b8 = 0; b8 < 8; b8++) acc[o8][b8] = 0.f;

        #pragma unroll
        for (int i = 0; i < 8; i++) {
            #pragma unroll
            for (int o8 = 0; o8 < 8; o8++) {
                float w = Ws[(i * 16 + oh * 8 + o8) * 33 + r];
                #pragma unroll
                for (int b8 = 0; b8 < 8; b8++)
                    acc[o8][b8] = fmaf(u_r[b8][i], w, acc[o8][b8]);
            }
        }

        #pragma unroll
        for (int b8 = 0; b8 < 8; b8++) {
            size_t base = ((size_t)((bg * 8 + b8) * NROUTE + rg) * NCAPS + c) * ODIM + oh * 8;
            float4 v0 = make_float4(acc[0][b8], acc[1][b8], acc[2][b8], acc[3][b8]);
            float4 v1 = make_float4(acc[4][b8], acc[5][b8], acc[6][b8], acc[7][b8]);
            *reinterpret_cast<float4*>(g_uhat + base)     = v0;
            *reinterpret_cast<float4*>(g_uhat + base + 4) = v1;
        }

        // S0 partial: reduce over the 32 r's held by this warp's lanes
        #pragma unroll
        for (int o8 = 0; o8 < 8; o8++) {
            #pragma unroll
            for (int b8 = 0; b8 < 8; b8++) {
                float v = acc[o8][b8];
                v += __shfl_down_sync(0xffffffffu, v, 16);
                v += __shfl_down_sync(0xffffffffu, v, 8);
                v += __shfl_down_sync(0xffffffffu, v, 4);
                v += __shfl_down_sync(0xffffffffu, v, 2);
                v += __shfl_down_sync(0xffffffffu, v, 1);
                if (r == 0)
                    atomicAdd(&g_S[((bg * 8 + b8) * NCAPS + c) * ODIM + oh * 8 + o8], v);
            }
        }
    }
}

// ---------------- squash: vsum = (mode? vsum : 0) + squash(g_S * mult) -----
__global__ void squash_kernel(float mult, int add_mode)
{
    int idx = blockIdx.x * blockDim.x + threadIdx.x;   // (b*50 + c)
    if (idx >= BATCH * NCAPS) return;
    const float* s = g_S + idx * ODIM;
    float sv[16], n2 = 0.f;
    #pragma unroll
    for (int o = 0; o < 16; o++) { sv[o] = s[o] * mult; n2 = fmaf(sv[o], sv[o], n2); }
    float n = sqrtf(n2);
    float f = n2 / ((1.f + n2) * (n + 1e-8f));
    float* vs = g_vsum + idx * ODIM;
    #pragma unroll
    for (int o = 0; o < 16; o++) {
        float v = f * sv[o];
        vs[o] = add_mode ? (vs[o] + v) : v;
    }
}

// ---------------- routing pass: coef = softmax_c(uhat . vsum); s += coef*uhat
// grid (96, 64): x = r-tile (32 rows), y = b. 256 threads = 8 warps x 4 rows.
__global__ __launch_bounds__(256) void route_pass_kernel()
{
    __shared__ float vs[NCAPS * 17];
    __shared__ float s_acc[CO];

    const int b  = blockIdx.y;
    const int r0 = blockIdx.x * 32;
    const int t  = threadIdx.x;

    for (int f = t; f < CO; f += 256) {
        int cc = f >> 4, oo = f & 15;
        vs[cc * 17 + oo] = g_vsum[b * CO + f];
        s_acc[f] = 0.f;
    }
    __syncthreads();

    const int warp = t >> 5, lane = t & 31;
    const int c1 = lane, c2 = lane + 32;
    const bool v2ok = (c2 < NCAPS);

    for (int j = 0; j < 4; j++) {
        int r = r0 + warp * 4 + j;
        size_t base = (size_t)(b * NROUTE + r) * CO;

        float uh1[16], uh2[16];
        const float4* p1 = reinterpret_cast<const float4*>(g_uhat + base + c1 * ODIM);
        #pragma unroll
        for (int q = 0; q < 4; q++) {
            float4 v = p1[q];
            uh1[4 * q] = v.x; uh1[4 * q + 1] = v.y; uh1[4 * q + 2] = v.z; uh1[4 * q + 3] = v.w;
        }
        float t2 = -1e30f;
        if (v2ok) {
            const float4* p2 = reinterpret_cast<const float4*>(g_uhat + base + c2 * ODIM);
            #pragma unroll
            for (int q = 0; q < 4; q++) {
                float4 v = p2[q];
                uh2[4 * q] = v.x; uh2[4 * q + 1] = v.y; uh2[4 * q + 2] = v.z; uh2[4 * q + 3] = v.w;
            }
        }

        float t1 = 0.f;
        #pragma unroll
        for (int o = 0; o < 16; o++) t1 = fmaf(uh1[o], vs[c1 * 17 + o], t1);
        if (v2ok) {
            float s2 = 0.f;
            #pragma unroll
            for (int o = 0; o < 16; o++) s2 = fmaf(uh2[o], vs[c2 * 17 + o], s2);
            t2 = s2;
        }

        float m = fmaxf(t1, t2);
        #pragma unroll
        for (int off = 16; off >= 1; off >>= 1)
            m = fmaxf(m, __shfl_xor_sync(0xffffffffu, m, off));
        float e1 = expf(t1 - m);
        float e2 = v2ok ? expf(t2 - m) : 0.f;
        float se = e1 + e2;
        #pragma unroll
        for (int off = 16; off >= 1; off >>= 1)
            se += __shfl_xor_sync(0xffffffffu, se, off);
        float inv = 1.f / se;
        float co1 = e1 * inv, co2 = e2 * inv;

        #pragma unroll
        for (int o = 0; o < 16; o++) atomicAdd(&s_acc[c1 * ODIM + o], co1 * uh1[o]);
        if (v2ok) {
            #pragma unroll
            for (int o = 0; o < 16; o++) atomicAdd(&s_acc[c2 * ODIM + o], co2 * uh2[o]);
        }
    }
    __syncthreads();
    for (int f = t; f < CO; f += 256) atomicAdd(&g_S[b * CO + f], s_acc[f]);
}

// ---------------- final: v = squash(s2), lengths, argmax, vtop -------------
// grid (BATCH), 64 threads
__global__ void final_kernel(float* __restrict__ out)
{
    __shared__ float v_s[NCAPS * ODIM];
    __shared__ float len_s[NCAPS];
    __shared__ int am_s;

    const int b = blockIdx.x, t = threadIdx.x;
    if (t < NCAPS) {
        const float* s = g_S + (b * NCAPS + t) * ODIM;
        float n2 = 0.f;
        float sv[16];
        #pragma unroll
        for (int o = 0; o < 16; o++) { sv[o] = s[o]; n2 = fmaf(sv[o], sv[o], n2); }
        float n = sqrtf(n2);
        float f = n2 / ((1.f + n2) * (n + 1e-8f));
        float l2 = 0.f;
        #pragma unroll
        for (int o = 0; o < 16; o++) {
            float v = f * sv[o];
            v_s[t * ODIM + o] = v;
            l2 = fmaf(v, v, l2);
        }
        float len = sqrtf(l2);
        len_s[t] = len;
        out[b * NCAPS + t] = len;   // lengths output, row-major (B, C)
    }
    __syncthreads();
    if (t == 0) {
        int best = 0; float bl = len_s[0];
        for (int c = 1; c < NCAPS; c++) if (len_s[c] > bl) { bl = len_s[c]; best = c; }
        am_s = best;
        g_amax[b] = best;
    }
    __syncthreads();
    if (t < ODIM) g_vtop[b * ODIM + t] = v_s[am_s * ODIM + t];
}

// ---------------- MLP layer 1 (exploits 16-sparse input) -------------------
// grid (BATCH), 512 threads
__global__ void mlp1_kernel(const float* __restrict__ w1, const float* __restrict__ b1)
{
    __shared__ float vt[ODIM];
    __shared__ int am;
    const int b = blockIdx.x, t = threadIdx.x;
    if (t < ODIM) vt[t] = g_vtop[b * ODIM + t];
    if (t == 0) am = g_amax[b];
    __syncthreads();
    float acc = b1[t];
    const int row0 = am * ODIM;
    #pragma unroll
    for (int o = 0; o < 16; o++) acc = fmaf(vt[o], w1[(row0 + o) * HID1 + t], acc);
    g_h1[b * HID1 + t] = acc > 0.f ? acc : 0.f;
}

// ---------------- MLP layer 2 ----------------------------------------------
// grid (4, 8): x = n-tile(256), y = b-tile(8). 256 threads.
__global__ __launch_bounds__(256) void mlp2_kernel(const float* __restrict__ w2,
                                                   const float* __restrict__ b2)
{
    __shared__ float h1s[8 * HID1];
    const int t = threadIdx.x;
    const int n = blockIdx.x * 256 + t;
    const int bb = blockIdx.y * 8;
    for (int f = t; f < 8 * HID1; f += 256) {
        int b8 = f >> 9, k = f & 511;
        h1s[f] = g_h1[(bb + b8) * HID1 + k];
    }
    __syncthreads();
    float acc[8];
    float bias = b2[n];
    #pragma unroll
    for (int b8 = 0; b8 < 8; b8++) acc[b8] = bias;
    #pragma unroll 4
    for (int k = 0; k < HID1; k++) {
        float w = w2[(size_t)k * HID2 + n];
        #pragma unroll
        for (int b8 = 0; b8 < 8; b8++) acc[b8] = fmaf(h1s[b8 * HID1 + k], w, acc[b8]);
    }
    #pragma unroll
    for (int b8 = 0; b8 < 8; b8++) {
        float v = acc[b8];
        g_h2[(bb + b8) * HID2 + n] = v > 0.f ? v : 0.f;
    }
}

// ---------------- MLP layer 3 + sigmoid -> recon ---------------------------
// grid (149, 4): x = n-tile(128), y = b-tile(16). 128 threads. dyn smem 64KB.
__global__ __launch_bounds__(128) void mlp3_kernel(const float* __restrict__ w3,
                                                   const float* __restrict__ b3,
                                                   float* __restrict__ recon)
{
    extern __shared__ float h2s[];   // [16][1024]
    const int t = threadIdx.x;
    const int n = blockIdx.x * 128 + t;
    const int bb = blockIdx.y * 16;
    for (int f = t; f < 16 * HID2; f += 128) {
        int b16 = f >> 10, k = f & 1023;
        h2s[f] = g_h2[(bb + b16) * HID2 + k];
    }
    __syncthreads();
    if (n >= NOUT) return;

    float acc[16];
    float bias = b3[n];
    #pragma unroll
    for (int b16 = 0; b16 < 16; b16++) acc[b16] = bias;

    for (int k0 = 0; k0 < HID2; k0 += 4) {
        float w0 = w3[(size_t)(k0 + 0) * NOUT + n];
        float w1v = w3[(size_t)(k0 + 1) * NOUT + n];
        float w2v = w3[(size_t)(k0 + 2) * NOUT + n];
        float w3v = w3[(size_t)(k0 + 3) * NOUT + n];
        #pragma unroll
        for (int b16 = 0; b16 < 16; b16++) {
            float4 h = *reinterpret_cast<const float4*>(&h2s[b16 * HID2 + k0]);
            float a = acc[b16];
            a = fmaf(h.x, w0, a);
            a = fmaf(h.y, w1v, a);
            a = fmaf(h.z, w2v, a);
            a = fmaf(h.w, w3v, a);
            acc[b16] = a;
        }
    }
    #pragma unroll
    for (int b16 = 0; b16 < 16; b16++) {
        float s = 1.f / (1.f + expf(-acc[b16]));
        recon[(size_t)(bb + b16) * NOUT + n] = s;
    }
}

// ---------------- launch ----------------------------------------------------
extern "C" void kernel_launch(void* const* d_in, const int* in_sizes, int n_in,
                              void* d_out, int out_size)
{
    const int*   x      = (const int*)  d_in[0];
    const float* emb    = (const float*)d_in[1];
    const float* conv_w = (const float*)d_in[2];
    const float* conv_b = (const float*)d_in[3];
    const float* W      = (const float*)d_in[4];
    const float* w1     = (const float*)d_in[5];
    const float* b1     = (const float*)d_in[6];
    const float* w2     = (const float*)d_in[7];
    const float* b2     = (const float*)d_in[8];
    const float* w3     = (const float*)d_in[9];
    const float* b3     = (const float*)d_in[10];
    float* out = (float*)d_out;
    // lengths at offset 0 (B*C floats); recon fills the remainder
    float* recon = out + ((size_t)out_size - (size_t)BATCH * NOUT);

    static int attr_done = 0;
    if (!attr_done) {
        cudaFuncSetAttribute(mlp3_kernel, cudaFuncAttributeMaxDynamicSharedMemorySize,
                             16 * HID2 * sizeof(float));
        attr_done = 1;
    }

    // 1. conv/embed -> u
    conv_embed_kernel<<<dim3(2, BATCH), 256>>>(x, emb, conv_w, conv_b);

    // 2. u_hat + fused S0
    zero_S_kernel<<<(BATCH * CO + 255) / 256, 256>>>();
    gen_uhat_kernel<<<dim3(96, NCAPS), 256>>>(W);

    // 3. v0 = squash(S0/50); vsum = v0
    squash_kernel<<<(BATCH * NCAPS + 127) / 128, 128>>>(1.f / (float)NCAPS, 0);

    // 4. s1 pass (coef from uhat.v0)
    zero_S_kernel<<<(BATCH * CO + 255) / 256, 256>>>();
    route_pass_kernel<<<dim3(96, BATCH), 256>>>();

    // 5. v1 = squash(s1); vsum += v1
    squash_kernel<<<(BATCH * NCAPS + 127) / 128, 128>>>(1.f, 1);

    // 6. s2 pass (coef from uhat.(v0+v1))
    zero_S_kernel<<<(BATCH * CO + 255) / 256, 256>>>();
    route_pass_kernel<<<dim3(96, BATCH), 256>>>();

    // 7. final v, lengths, argmax, vtop
    final_kernel<<<BATCH, 64>>>(out);

    // 8. MLP + sigmoid
    mlp1_kernel<<<BATCH, HID1>>>(w1, b1);
    mlp2_kernel<<<dim3(HID2 / 256, BATCH / 8), 256>>>(w2, b2);
    mlp3_kernel<<<dim3((NOUT + 127) / 128, BATCH / 16), 128,
                 16 * HID2 * sizeof(float)>>>(w3, b3, recon);
}

// round 2
// speedup vs baseline: 2.0554x; 2.0554x over previous
#include <cuda_runtime.h>
#include <math.h>
#include <stdint.h>

// ---------------- problem constants ----------------
#define BATCH   64
#define SEQ     200
#define EMBED   64
#define VOCAB   95
#define LOUT    96          // (200-9)/2+1
#define NCAPS   50
#define CAPSD   8
#define ODIM    16
#define NROUTE  3072        // 32 * LOUT
#define HID1    512
#define HID2    1024
#define NOUT    19000       // SEQ*VOCAB
#define CO      (NCAPS*ODIM)   // 800
#define J7      7              // ceil(800/128)

// ---------------- device scratch ----------------
__device__ float g_u[BATCH * NROUTE * CAPSD];                   // 6.3 MB
__device__ float g_uhat[(size_t)BATCH * NROUTE * NCAPS * ODIM]; // 629 MB
__device__ float g_S[BATCH * CO];
__device__ float g_vsum[BATCH * CO];
__device__ float g_vtop[BATCH * ODIM];
__device__ int   g_amax[BATCH];
__device__ float g_h1[BATCH * HID1];
__device__ float g_h2[BATCH * HID2];

// ---------------- kernel 1: embedding + conv1d + relu -> u ----------------
// grid (4, BATCH): x = l-quarter (24 outputs), y = b. 256 threads = channels.
__global__ __launch_bounds__(256) void conv_embed_kernel(
    const int* __restrict__ x, const float* __restrict__ emb,
    const float* __restrict__ cw, const float* __restrict__ cb)
{
    __shared__ int   xs[56];
    __shared__ float se[56 * EMBED];

    const int l0 = blockIdx.x * 24;
    const int b  = blockIdx.y;
    const int t  = threadIdx.x;

    if (t < 55) xs[t] = x[b * SEQ + 2 * l0 + t];
    __syncthreads();
    for (int f = t; f < 55 * EMBED; f += 256) {
        int s = f >> 6, ic = f & 63;
        se[f] = emb[xs[s] * EMBED + ic];
    }
    __syncthreads();

    const int ch = t;
    float acc[24];
    {
        float bias = cb[ch];
        #pragma unroll
        for (int j = 0; j < 24; j++) acc[j] = bias;
    }

    const float* cwr = cw + (size_t)ch * (EMBED * 9);
    for (int ic = 0; ic < EMBED; ic++) {
        float w_r[9];
        #pragma unroll
        for (int k = 0; k < 9; k++) w_r[k] = __ldg(cwr + ic * 9 + k);
        #pragma unroll
        for (int lt = 0; lt < 3; lt++) {
            float se_r[23];
            #pragma unroll
            for (int q = 0; q < 23; q++) se_r[q] = se[(lt * 16 + q) * EMBED + ic];
            #pragma unroll
            for (int j = 0; j < 8; j++) {
                float a = acc[lt * 8 + j];
                #pragma unroll
                for (int k = 0; k < 9; k++) a = fmaf(se_r[2 * j + k], w_r[k], a);
                acc[lt * 8 + j] = a;
            }
        }
    }

    const int g = ch >> 3, i = ch & 7;
    #pragma unroll
    for (int j = 0; j < 24; j++) {
        int l = l0 + j;
        float v = acc[j];
        v = v > 0.f ? v : 0.f;
        g_u[((size_t)(b * NROUTE) + g * LOUT + l) * CAPSD + i] = v;
    }
}

// ---------------- zero g_S ----------------
__global__ void zero_S_kernel() {
    int i = blockIdx.x * blockDim.x + threadIdx.x;
    if (i < BATCH * CO) g_S[i] = 0.f;
}

// ---------------- kernel 2: u_hat generation + fused S0 ----
// grid (96, 50): x = r-tile (32 routes), y = c. 256 threads = 8 warps.
// lane = r. warp handles 8 batches in 2 groups of 4. Staged coalesced stores.
__global__ __launch_bounds__(256, 1) void gen_uhat_kernel(const float* __restrict__ W)
{
    __shared__ float Ws[32 * 132];       // [r][io], row pad 132 (16B-aligned rows)
    __shared__ float stage[8][32 * 20];  // per-warp transpose buffer

    const int r0 = blockIdx.x * 32;
    const int c  = blockIdx.y;
    const int t  = threadIdx.x;

    for (int f = t; f < 32 * 128; f += 256) {
        int rl = f >> 7, io = f & 127;
        Ws[rl * 132 + io] = W[((size_t)(c * NROUTE + r0 + rl)) * 128 + io];
    }
    __syncthreads();

    const int r    = t & 31;
    const int warp = t >> 5;
    const int oq   = r & 3;
    const int rsub = r >> 2;
    float* st = stage[warp];

    #pragma unroll
    for (int g4 = 0; g4 < 2; g4++) {
        float u_r[4][8];
        #pragma unroll
        for (int b4 = 0; b4 < 4; b4++) {
            int b = warp * 8 + g4 * 4 + b4;
            const float4* up = reinterpret_cast<const float4*>(
                g_u + ((size_t)(b * NROUTE + r0 + r)) * CAPSD);
            float4 a = up[0], q = up[1];
            u_r[b4][0] = a.x; u_r[b4][1] = a.y; u_r[b4][2] = a.z; u_r[b4][3] = a.w;
            u_r[b4][4] = q.x; u_r[b4][5] = q.y; u_r[b4][6] = q.z; u_r[b4][7] = q.w;
        }

        float acc[4][16];
        #pragma unroll
        for (int b4 = 0; b4 < 4; b4++)
            #pragma unroll
            for (int o = 0; o < 16; o++) acc[b4][o] = 0.f;

        #pragma unroll
        for (int i = 0; i < 8; i++) {
            #pragma unroll
            for (int o4 = 0; o4 < 4; o4++) {
                float4 w = *reinterpret_cast<const float4*>(&Ws[r * 132 + i * 16 + o4 * 4]);
                #pragma unroll
                for (int b4 = 0; b4 < 4; b4++) {
                    float ui = u_r[b4][i];
                    acc[b4][o4 * 4 + 0] = fmaf(ui, w.x, acc[b4][o4 * 4 + 0]);
                    acc[b4][o4 * 4 + 1] = fmaf(ui, w.y, acc[b4][o4 * 4 + 1]);
                    acc[b4][o4 * 4 + 2] = fmaf(ui, w.z, acc[b4][o4 * 4 + 2]);
                    acc[b4][o4 * 4 + 3] = fmaf(ui, w.w, acc[b4][o4 * 4 + 3]);
                }
            }
        }

        #pragma unroll
        for (int b4 = 0; b4 < 4; b4++) {
            int b = warp * 8 + g4 * 4 + b4;

            // S0 partial = sum over this warp's 32 r's
            #pragma unroll
            for (int o = 0; o < 16; o++) {
                float v = acc[b4][o];
                v += __shfl_down_sync(0xffffffffu, v, 16);
                v += __shfl_down_sync(0xffffffffu, v, 8);
                v += __shfl_down_sync(0xffffffffu, v, 4);
                v += __shfl_down_sync(0xffffffffu, v, 2);
                v += __shfl_down_sync(0xffffffffu, v, 1);
                if (r == 0) atomicAdd(&g_S[(b * NCAPS + c) * ODIM + o], v);
            }

            // stage [r][o] then coalesced 64B-chunk stores (8 chunks/instr)
            __syncwarp();
            *reinterpret_cast<float4*>(&st[r * 20 + 0])  =
                make_float4(acc[b4][0], acc[b4][1], acc[b4][2], acc[b4][3]);
            *reinterpret_cast<float4*>(&st[r * 20 + 4])  =
                make_float4(acc[b4][4], acc[b4][5], acc[b4][6], acc[b4][7]);
            *reinterpret_cast<float4*>(&st[r * 20 + 8])  =
                make_float4(acc[b4][8], acc[b4][9], acc[b4][10], acc[b4][11]);
            *reinterpret_cast<float4*>(&st[r * 20 + 12]) =
                make_float4(acc[b4][12], acc[b4][13], acc[b4][14], acc[b4][15]);
            __syncwarp();

            size_t cb = ((size_t)b * NROUTE + r0) * CO + (size_t)c * ODIM + oq * 4;
            #pragma unroll
            for (int k = 0; k < 4; k++) {
                int rr = k * 8 + rsub;
                float4 v = *reinterpret_cast<const float4*>(&st[rr * 20 + oq * 4]);
                *reinterpret_cast<float4*>(g_uhat + cb + (size_t)rr * CO) = v;
            }
            __syncwarp();
        }
    }
}

// ---------------- squash: vsum update + zero g_S ---------------------------
__global__ void squash_kernel(float mult, int add_mode)
{
    int idx = blockIdx.x * blockDim.x + threadIdx.x;   // (b*50 + c)
    if (idx >= BATCH * NCAPS) return;
    float* s = g_S + idx * ODIM;
    float sv[16], n2 = 0.f;
    #pragma unroll
    for (int o = 0; o < 16; o++) { sv[o] = s[o] * mult; n2 = fmaf(sv[o], sv[o], n2); }
    float n = sqrtf(n2);
    float f = n2 / ((1.f + n2) * (n + 1e-8f));
    float* vs = g_vsum + idx * ODIM;
    #pragma unroll
    for (int o = 0; o < 16; o++) {
        float v = f * sv[o];
        vs[o] = add_mode ? (vs[o] + v) : v;
        s[o] = 0.f;   // zero for the next routing pass
    }
}

// ---------------- routing pass ---------------------------------------------
// coef = softmax_c(uhat . vsum); s += coef*uhat.  Register accumulation.
// grid (96, 64): x = r-tile (32 r), y = b. 256 threads = 8 warps x 4 r.
// Warp reads the 800-float (b,r) row linearly: lane*4 + j7*128 -> (c,o-quad).
__global__ __launch_bounds__(256, 2) void route_pass_kernel()
{
    __shared__ float sred[8][CO];

    const int b    = blockIdx.y;
    const int r0   = blockIdx.x * 32;
    const int t    = threadIdx.x;
    const int warp = t >> 5, lane = t & 31;

    float vsq[J7][4], acc[J7][4];
    #pragma unroll
    for (int j7 = 0; j7 < J7; j7++) {
        int f = j7 * 128 + lane * 4;
        if (f < CO) {
            float4 v = *reinterpret_cast<const float4*>(g_vsum + b * CO + f);
            vsq[j7][0] = v.x; vsq[j7][1] = v.y; vsq[j7][2] = v.z; vsq[j7][3] = v.w;
        } else {
            vsq[j7][0] = vsq[j7][1] = vsq[j7][2] = vsq[j7][3] = 0.f;
        }
        acc[j7][0] = acc[j7][1] = acc[j7][2] = acc[j7][3] = 0.f;
    }

    for (int j = 0; j < 4; j++) {
        int r = r0 + warp * 4 + j;
        size_t base = ((size_t)b * NROUTE + r) * CO;

        float uh[J7][4], tj[J7];
        #pragma unroll
        for (int j7 = 0; j7 < J7; j7++) {
            int f = j7 * 128 + lane * 4;
            bool valid = (f < CO);
            float4 v = make_float4(0.f, 0.f, 0.f, 0.f);
            if (valid) v = *reinterpret_cast<const float4*>(g_uhat + base + f);
            uh[j7][0] = v.x; uh[j7][1] = v.y; uh[j7][2] = v.z; uh[j7][3] = v.w;
            float d = uh[j7][0] * vsq[j7][0];
            d = fmaf(uh[j7][1], vsq[j7][1], d);
            d = fmaf(uh[j7][2], vsq[j7][2], d);
            d = fmaf(uh[j7][3], vsq[j7][3], d);
            d += __shfl_xor_sync(0xffffffffu, d, 1);
            d += __shfl_xor_sync(0xffffffffu, d, 2);
            tj[j7] = valid ? d : -1e30f;
        }

        float m = tj[0];
        #pragma unroll
        for (int j7 = 1; j7 < J7; j7++) m = fmaxf(m, tj[j7]);
        #pragma unroll
        for (int off = 16; off >= 1; off >>= 1)
            m = fmaxf(m, __shfl_xor_sync(0xffffffffu, m, off));

        float ej[J7], es = 0.f;
        #pragma unroll
        for (int j7 = 0; j7 < J7; j7++) { ej[j7] = __expf(tj[j7] - m); es += ej[j7]; }
        #pragma unroll
        for (int off = 16; off >= 1; off >>= 1)
            es += __shfl_xor_sync(0xffffffffu, es, off);
        // every valid c appears on exactly 4 lanes -> Z = es/4
        float cs = 4.f / es;

        #pragma unroll
        for (int j7 = 0; j7 < J7; j7++) {
            float cf = ej[j7] * cs;
            acc[j7][0] = fmaf(cf, uh[j7][0], acc[j7][0]);
            acc[j7][1] = fmaf(cf, uh[j7][1], acc[j7][1]);
            acc[j7][2] = fmaf(cf, uh[j7][2], acc[j7][2]);
            acc[j7][3] = fmaf(cf, uh[j7][3], acc[j7][3]);
        }
    }

    #pragma unroll
    for (int j7 = 0; j7 < J7; j7++) {
        int f = j7 * 128 + lane * 4;
        if (f < CO)
            *reinterpret_cast<float4*>(&sred[warp][f]) =
                make_float4(acc[j7][0], acc[j7][1], acc[j7][2], acc[j7][3]);
    }
    __syncthreads();

    if (t < CO / 4) {
        int f = t * 4;
        float s0 = 0.f, s1 = 0.f, s2 = 0.f, s3 = 0.f;
        #pragma unroll
        for (int w = 0; w < 8; w++) {
            float4 v = *reinterpret_cast<const float4*>(&sred[w][f]);
            s0 += v.x; s1 += v.y; s2 += v.z; s3 += v.w;
        }
        float* dst = g_S + b * CO + f;
        atomicAdd(dst + 0, s0);
        atomicAdd(dst + 1, s1);
        atomicAdd(dst + 2, s2);
        atomicAdd(dst + 3, s3);
    }
}

// ---------------- final: v = squash(s2), lengths, argmax, vtop -------------
__global__ void final_kernel(float* __restrict__ out)
{
    __shared__ float v_s[NCAPS * ODIM];
    __shared__ float len_s[NCAPS];
    __shared__ int am_s;

    const int b = blockIdx.x, t = threadIdx.x;
    if (t < NCAPS) {
        const float* s = g_S + (b * NCAPS + t) * ODIM;
        float n2 = 0.f;
        float sv[16];
        #pragma unroll
        for (int o = 0; o < 16; o++) { sv[o] = s[o]; n2 = fmaf(sv[o], sv[o], n2); }
        float n = sqrtf(n2);
        float f = n2 / ((1.f + n2) * (n + 1e-8f));
        float l2 = 0.f;
        #pragma unroll
        for (int o = 0; o < 16; o++) {
            float v = f * sv[o];
            v_s[t * ODIM + o] = v;
            l2 = fmaf(v, v, l2);
        }
        float len = sqrtf(l2);
        len_s[t] = len;
        out[b * NCAPS + t] = len;
    }
    __syncthreads();
    if (t == 0) {
        int best = 0; float bl = len_s[0];
        for (int c = 1; c < NCAPS; c++) if (len_s[c] > bl) { bl = len_s[c]; best = c; }
        am_s = best;
        g_amax[b] = best;
    }
    __syncthreads();
    if (t < ODIM) g_vtop[b * ODIM + t] = v_s[am_s * ODIM + t];
}

// ---------------- MLP layer 1 (16-sparse input) ----------------------------
__global__ void mlp1_kernel(const float* __restrict__ w1, const float* __restrict__ b1)
{
    __shared__ float vt[ODIM];
    __shared__ int am;
    const int b = blockIdx.x, t = threadIdx.x;
    if (t < ODIM) vt[t] = g_vtop[b * ODIM + t];
    if (t == 0) am = g_amax[b];
    __syncthreads();
    float acc = b1[t];
    const int row0 = am * ODIM;
    #pragma unroll
    for (int o = 0; o < 16; o++) acc = fmaf(vt[o], w1[(row0 + o) * HID1 + t], acc);
    g_h1[b * HID1 + t] = acc > 0.f ? acc : 0.f;
}

// ---------------- MLP layer 2 ----------------------------------------------
__global__ __launch_bounds__(256) void mlp2_kernel(const float* __restrict__ w2,
                                                   const float* __restrict__ b2)
{
    __shared__ float h1s[8 * HID1];
    const int t = threadIdx.x;
    const int n = blockIdx.x * 256 + t;
    const int bb = blockIdx.y * 8;
    for (int f = t; f < 8 * HID1; f += 256) {
        int b8 = f >> 9, k = f & 511;
        h1s[f] = g_h1[(bb + b8) * HID1 + k];
    }
    __syncthreads();
    float acc[8];
    float bias = b2[n];
    #pragma unroll
    for (int b8 = 0; b8 < 8; b8++) acc[b8] = bias;
    #pragma unroll 4
    for (int k = 0; k < HID1; k++) {
        float w = w2[(size_t)k * HID2 + n];
        #pragma unroll
        for (int b8 = 0; b8 < 8; b8++) acc[b8] = fmaf(h1s[b8 * HID1 + k], w, acc[b8]);
    }
    #pragma unroll
    for (int b8 = 0; b8 < 8; b8++) {
        float v = acc[b8];
        g_h2[(bb + b8) * HID2 + n] = v > 0.f ? v : 0.f;
    }
}

// ---------------- MLP layer 3 + sigmoid -> recon ---------------------------
__global__ __launch_bounds__(128) void mlp3_kernel(const float* __restrict__ w3,
                                                   const float* __restrict__ b3,
                                                   float* __restrict__ recon)
{
    extern __shared__ float h2s[];   // [16][1024]
    const int t = threadIdx.x;
    const int n = blockIdx.x * 128 + t;
    const int bb = blockIdx.y * 16;
    for (int f = t; f < 16 * HID2; f += 128) {
        int b16 = f >> 10, k = f & 1023;
        h2s[f] = g_h2[(bb + b16) * HID2 + k];
    }
    __syncthreads();
    if (n >= NOUT) return;

    float acc[16];
    float bias = b3[n];
    #pragma unroll
    for (int b16 = 0; b16 < 16; b16++) acc[b16] = bias;

    for (int k0 = 0; k0 < HID2; k0 += 4) {
        float w0 = w3[(size_t)(k0 + 0) * NOUT + n];
        float w1v = w3[(size_t)(k0 + 1) * NOUT + n];
        float w2v = w3[(size_t)(k0 + 2) * NOUT + n];
        float w3v = w3[(size_t)(k0 + 3) * NOUT + n];
        #pragma unroll
        for (int b16 = 0; b16 < 16; b16++) {
            float4 h = *reinterpret_cast<const float4*>(&h2s[b16 * HID2 + k0]);
            float a = acc[b16];
            a = fmaf(h.x, w0, a);
            a = fmaf(h.y, w1v, a);
            a = fmaf(h.z, w2v, a);
            a = fmaf(h.w, w3v, a);
            acc[b16] = a;
        }
    }
    #pragma unroll
    for (int b16 = 0; b16 < 16; b16++) {
        float s = 1.f / (1.f + expf(-acc[b16]));
        recon[(size_t)(bb + b16) * NOUT + n] = s;
    }
}

// ---------------- launch ----------------------------------------------------
extern "C" void kernel_launch(void* const* d_in, const int* in_sizes, int n_in,
                              void* d_out, int out_size)
{
    const int*   x      = (const int*)  d_in[0];
    const float* emb    = (const float*)d_in[1];
    const float* conv_w = (const float*)d_in[2];
    const float* conv_b = (const float*)d_in[3];
    const float* W      = (const float*)d_in[4];
    const float* w1     = (const float*)d_in[5];
    const float* b1     = (const float*)d_in[6];
    const float* w2     = (const float*)d_in[7];
    const float* b2     = (const float*)d_in[8];
    const float* w3     = (const float*)d_in[9];
    const float* b3     = (const float*)d_in[10];
    float* out = (float*)d_out;
    float* recon = out + ((size_t)out_size - (size_t)BATCH * NOUT);

    static int attr_done = 0;
    if (!attr_done) {
        cudaFuncSetAttribute(mlp3_kernel, cudaFuncAttributeMaxDynamicSharedMemorySize,
                             16 * HID2 * sizeof(float));
        attr_done = 1;
    }

    // 1. conv/embed -> u
    conv_embed_kernel<<<dim3(4, BATCH), 256>>>(x, emb, conv_w, conv_b);

    // 2. u_hat + fused S0
    zero_S_kernel<<<(BATCH * CO + 255) / 256, 256>>>();
    gen_uhat_kernel<<<dim3(96, NCAPS), 256>>>(W);

    // 3. v0 = squash(S0/50); vsum = v0 (also zeroes g_S)
    squash_kernel<<<(BATCH * NCAPS + 127) / 128, 128>>>(1.f / (float)NCAPS, 0);

    // 4. s1 pass
    route_pass_kernel<<<dim3(96, BATCH), 256>>>();

    // 5. v1 = squash(s1); vsum += v1 (also zeroes g_S)
    squash_kernel<<<(BATCH * NCAPS + 127) / 128, 128>>>(1.f, 1);

    // 6. s2 pass
    route_pass_kernel<<<dim3(96, BATCH), 256>>>();

    // 7. final v, lengths, argmax, vtop
    final_kernel<<<BATCH, 64>>>(out);

    // 8. MLP + sigmoid
    mlp1_kernel<<<BATCH, HID1>>>(w1, b1);
    mlp2_kernel<<<dim3(HID2 / 256, BATCH / 8), 256>>>(w2, b2);
    mlp3_kernel<<<dim3((NOUT + 127) / 128, BATCH / 16), 128,
                 16 * HID2 * sizeof(float)>>>(w3, b3, recon);
}

// round 4
// speedup vs baseline: 2.6182x; 1.2738x over previous
#include <cuda_runtime.h>
#include <math.h>
#include <stdint.h>

// ---------------- problem constants ----------------
#define BATCH   64
#define SEQ     200
#define EMBED   64
#define VOCAB   95
#define LOUT    96
#define NCAPS   50
#define CAPSD   8
#define ODIM    16
#define NROUTE  3072
#define HID1    512
#define HID2    1024
#define NOUT    19000
#define CO      (NCAPS*ODIM)     // 800

// routing-recompute tiling
#define RT_PHASE 2                      // routes per smem tile
#define R_LOOP   16                     // routes per block
#define NPHASE   (R_LOOP/RT_PHASE)      // 8
#define GX       (NROUTE/R_LOOP)        // 192
#define BT       16                     // batches per block (8 warps x 2)
#define WROW     144                    // padded floats per c-row (conflict-free LDS.128)
#define WTILE    (RT_PHASE*NCAPS*WROW)  // 14400 floats per buffer
#define VS_OFF   (2*WTILE)              // 28800 floats
#define SMEM_FLOATS (2*WTILE + BT*CO + 256)

// ---------------- device scratch ----------------
__device__ float g_u[BATCH * NROUTE * CAPSD];            // 6.3 MB
__device__ float g_Spart[(size_t)GX * BATCH * CO];       // 39.3 MB partial s
__device__ float g_vsum[BATCH * CO];
__device__ float g_vtop[BATCH * ODIM];
__device__ int   g_amax[BATCH];
__device__ float g_h1[BATCH * HID1];
__device__ float g_h2[BATCH * HID2];

// ---------------- kernel 1: embedding + conv1d + relu -> u ----------------
// grid (4, BATCH): x = l-quarter (24 outputs each), y = b. 256 threads = channels.
__global__ __launch_bounds__(256) void conv_embed_kernel(
    const int* __restrict__ x, const float* __restrict__ emb,
    const float* __restrict__ cw, const float* __restrict__ cb)
{
    __shared__ int   xs[56];
    __shared__ float se[56 * EMBED];

    const int l0 = blockIdx.x * 24;
    const int b  = blockIdx.y;
    const int t  = threadIdx.x;

    if (t < 55) xs[t] = x[b * SEQ + 2 * l0 + t];
    __syncthreads();
    for (int f = t; f < 55 * EMBED; f += 256) {
        int s = f >> 6, ic = f & 63;
        se[f] = emb[xs[s] * EMBED + ic];
    }
    __syncthreads();

    const int ch = t;
    float acc[24];
    {
        float bias = cb[ch];
        #pragma unroll
        for (int j = 0; j < 24; j++) acc[j] = bias;
    }

    const float* cwr = cw + (size_t)ch * (EMBED * 9);
    for (int ic = 0; ic < EMBED; ic++) {
        float w_r[9];
        #pragma unroll
        for (int k = 0; k < 9; k++) w_r[k] = __ldg(cwr + ic * 9 + k);
        #pragma unroll
        for (int lt = 0; lt < 3; lt++) {
            float se_r[23];
            #pragma unroll
            for (int q = 0; q < 23; q++) se_r[q] = se[(lt * 16 + q) * EMBED + ic];
            #pragma unroll
            for (int j = 0; j < 8; j++) {
                float a = acc[lt * 8 + j];
                #pragma unroll
                for (int k = 0; k < 9; k++) a = fmaf(se_r[2 * j + k], w_r[k], a);
                acc[lt * 8 + j] = a;
            }
        }
    }

    const int g = ch >> 3, i = ch & 7;
    #pragma unroll
    for (int j = 0; j < 24; j++) {
        int l = l0 + j;
        float v = acc[j];
        v = v > 0.f ? v : 0.f;
        g_u[((size_t)(b * NROUTE) + g * LOUT + l) * CAPSD + i] = v;
    }
}

// ---------------- routing by recompute -------------------------------------
// MODE 0: coef = 1 (uniform, scaled later); MODE 1: coef = softmax_c(uhat.vsum)
// grid (GX, 4). 256 threads = 8 warps x (2 batches). Warp loops 16 routes.
// Lane quad mapping: slot v = j*32+lane covers floats 4v..4v+3 of the 800-float
// (c,o) row; c = v>>2, valid while v < 200.
template<int MODE>
__global__ __launch_bounds__(256) void route_kernel(const float* __restrict__ W)
{
    extern __shared__ float sm[];
    const int gx    = blockIdx.x;
    const int b0blk = blockIdx.y * BT;
    const int t     = threadIdx.x;
    const int warp  = t >> 5, lane = t & 31;
    const int rbase = gx * R_LOOP;

    if (MODE) {
        const float4* src = reinterpret_cast<const float4*>(g_vsum + b0blk * CO);
        float4* dst = reinterpret_cast<float4*>(sm + VS_OFF);
        for (int i = t; i < BT * CO / 4; i += 256) dst[i] = src[i];
    }

    const int bA = b0blk + warp * 2;
    const int bB = bA + 1;

    float4 acc0[7], acc1[7];
    #pragma unroll
    for (int j = 0; j < 7; j++) {
        acc0[j] = make_float4(0.f, 0.f, 0.f, 0.f);
        acc1[j] = make_float4(0.f, 0.f, 0.f, 0.f);
    }

    // ---- prefetch tile 0
    {
        float* dstbase = sm;
        const int rp = rbase;
        for (int idx = t; idx < RT_PHASE * NCAPS * 32; idx += 256) {
            int rl = idx / (NCAPS * 32);
            int rem = idx - rl * (NCAPS * 32);
            int c = rem >> 5, k = rem & 31;
            const float* src = W + ((size_t)(c * NROUTE + rp + rl)) * 128 + k * 4;
            float* dst = dstbase + rl * (NCAPS * WROW) + c * WROW + k * 4;
            uint32_t ds = (uint32_t)__cvta_generic_to_shared(dst);
            asm volatile("cp.async.ca.shared.global [%0], [%1], 16;\n" :: "r"(ds), "l"(src));
        }
        asm volatile("cp.async.commit_group;\n");
    }

    for (int p = 0; p < NPHASE; p++) {
        if (p + 1 < NPHASE) {
            float* dstbase = sm + ((p + 1) & 1) * WTILE;
            const int rp = rbase + (p + 1) * RT_PHASE;
            for (int idx = t; idx < RT_PHASE * NCAPS * 32; idx += 256) {
                int rl = idx / (NCAPS * 32);
                int rem = idx - rl * (NCAPS * 32);
                int c = rem >> 5, k = rem & 31;
                const float* src = W + ((size_t)(c * NROUTE + rp + rl)) * 128 + k * 4;
                float* dst = dstbase + rl * (NCAPS * WROW) + c * WROW + k * 4;
                uint32_t ds = (uint32_t)__cvta_generic_to_shared(dst);
                asm volatile("cp.async.ca.shared.global [%0], [%1], 16;\n" :: "r"(ds), "l"(src));
            }
            asm volatile("cp.async.commit_group;\n");
            asm volatile("cp.async.wait_group 1;\n");
        } else {
            asm volatile("cp.async.wait_group 0;\n");
        }
        __syncthreads();

        const float* wbuf = sm + (p & 1) * WTILE;

        #pragma unroll
        for (int rl = 0; rl < RT_PHASE; rl++) {
            const int r = rbase + p * RT_PHASE + rl;

            float u0[8], u1[8];
            {
                const float4* upA = reinterpret_cast<const float4*>(
                    g_u + ((size_t)(bA * NROUTE + r)) * CAPSD);
                float4 a = upA[0], q = upA[1];
                u0[0]=a.x; u0[1]=a.y; u0[2]=a.z; u0[3]=a.w;
                u0[4]=q.x; u0[5]=q.y; u0[6]=q.z; u0[7]=q.w;
                const float4* upB = reinterpret_cast<const float4*>(
                    g_u + ((size_t)(bB * NROUTE + r)) * CAPSD);
                float4 c2 = upB[0], d2 = upB[1];
                u1[0]=c2.x; u1[1]=c2.y; u1[2]=c2.z; u1[3]=c2.w;
                u1[4]=d2.x; u1[5]=d2.y; u1[6]=d2.z; u1[7]=d2.w;
            }

            const float* wr = wbuf + rl * (NCAPS * WROW);
            float4 uh0[7], uh1[7];
            #pragma unroll
            for (int j = 0; j < 7; j++) {
                int v = j * 32 + lane;
                const float* wc = wr + (v >> 2) * WROW + (v & 3) * 4;
                float4 a0 = make_float4(0.f,0.f,0.f,0.f);
                float4 a1 = make_float4(0.f,0.f,0.f,0.f);
                #pragma unroll
                for (int i = 0; i < 8; i++) {
                    float4 w4 = *reinterpret_cast<const float4*>(wc + i * 16);
                    a0.x = fmaf(u0[i], w4.x, a0.x); a0.y = fmaf(u0[i], w4.y, a0.y);
                    a0.z = fmaf(u0[i], w4.z, a0.z); a0.w = fmaf(u0[i], w4.w, a0.w);
                    a1.x = fmaf(u1[i], w4.x, a1.x); a1.y = fmaf(u1[i], w4.y, a1.y);
                    a1.z = fmaf(u1[i], w4.z, a1.z); a1.w = fmaf(u1[i], w4.w, a1.w);
                }
                uh0[j] = a0; uh1[j] = a1;
            }

            if (MODE) {
                const float* vsA = sm + VS_OFF + (warp * 2) * CO;
                const float* vsB = vsA + CO;
                float d0[7], d1[7];
                #pragma unroll
                for (int j = 0; j < 7; j++) {
                    int v = j * 32 + lane;
                    float4 xa = *reinterpret_cast<const float4*>(vsA + 4 * v);
                    float4 xb = *reinterpret_cast<const float4*>(vsB + 4 * v);
                    float da = uh0[j].x * xa.x;
                    da = fmaf(uh0[j].y, xa.y, da);
                    da = fmaf(uh0[j].z, xa.z, da);
                    da = fmaf(uh0[j].w, xa.w, da);
                    float db = uh1[j].x * xb.x;
                    db = fmaf(uh1[j].y, xb.y, db);
                    db = fmaf(uh1[j].z, xb.z, db);
                    db = fmaf(uh1[j].w, xb.w, db);
                    da += __shfl_xor_sync(0xffffffffu, da, 1);
                    da += __shfl_xor_sync(0xffffffffu, da, 2);
                    db += __shfl_xor_sync(0xffffffffu, db, 1);
                    db += __shfl_xor_sync(0xffffffffu, db, 2);
                    bool valid = (v < 200);
                    d0[j] = valid ? da : -1e30f;
                    d1[j] = valid ? db : -1e30f;
                }
                float m0 = d0[0], m1 = d1[0];
                #pragma unroll
                for (int j = 1; j < 7; j++) { m0 = fmaxf(m0, d0[j]); m1 = fmaxf(m1, d1[j]); }
                #pragma unroll
                for (int off = 16; off >= 1; off >>= 1) {
                    m0 = fmaxf(m0, __shfl_xor_sync(0xffffffffu, m0, off));
                    m1 = fmaxf(m1, __shfl_xor_sync(0xffffffffu, m1, off));
                }
                float z0 = 0.f, z1 = 0.f;
                #pragma unroll
                for (int j = 0; j < 7; j++) {
                    int v = j * 32 + lane;
                    float e0 = (v < 200) ? __expf(d0[j] - m0) : 0.f;
                    float e1 = (v < 200) ? __expf(d1[j] - m1) : 0.f;
                    d0[j] = e0; d1[j] = e1;
                    z0 += e0; z1 += e1;
                }
                #pragma unroll
                for (int off = 16; off >= 1; off >>= 1) {
                    z0 += __shfl_xor_sync(0xffffffffu, z0, off);
                    z1 += __shfl_xor_sync(0xffffffffu, z1, off);
                }
                float s0 = 4.f / z0, s1 = 4.f / z1;   // each c duplicated on 4 lanes
                #pragma unroll
                for (int j = 0; j < 7; j++) {
                    float c0 = d0[j] * s0, c1 = d1[j] * s1;
                    acc0[j].x = fmaf(c0, uh0[j].x, acc0[j].x);
                    acc0[j].y = fmaf(c0, uh0[j].y, acc0[j].y);
                    acc0[j].z = fmaf(c0, uh0[j].z, acc0[j].z);
                    acc0[j].w = fmaf(c0, uh0[j].w, acc0[j].w);
                    acc1[j].x = fmaf(c1, uh1[j].x, acc1[j].x);
                    acc1[j].y = fmaf(c1, uh1[j].y, acc1[j].y);
                    acc1[j].z = fmaf(c1, uh1[j].z, acc1[j].z);
                    acc1[j].w = fmaf(c1, uh1[j].w, acc1[j].w);
                }
            } else {
                #pragma unroll
                for (int j = 0; j < 7; j++) {
                    acc0[j].x += uh0[j].x; acc0[j].y += uh0[j].y;
                    acc0[j].z += uh0[j].z; acc0[j].w += uh0[j].w;
                    acc1[j].x += uh1[j].x; acc1[j].y += uh1[j].y;
                    acc1[j].z += uh1[j].z; acc1[j].w += uh1[j].w;
                }
            }
        }
        __syncthreads();
    }

    // write partial s (coalesced float4, no atomics)
    float* pA = g_Spart + ((size_t)gx * BATCH + bA) * CO;
    float* pB = g_Spart + ((size_t)gx * BATCH + bB) * CO;
    #pragma unroll
    for (int j = 0; j < 7; j++) {
        int v = j * 32 + lane;
        if (v < 200) {
            *reinterpret_cast<float4*>(pA + 4 * v) = acc0[j];
            *reinterpret_cast<float4*>(pB + 4 * v) = acc1[j];
        }
    }
}

// ---------------- squash over partials: vsum = (add? vsum:0) + squash(sum*mult)
// thread per (b,c,quad): 12800 threads exactly (50 blocks x 256).
__global__ __launch_bounds__(256) void squash_partials_kernel(float mult, int add_mode)
{
    int idx = blockIdx.x * blockDim.x + threadIdx.x;
    int q = idx & 3, bc = idx >> 2;
    int b = bc / NCAPS, c = bc - b * NCAPS;

    float4 s = make_float4(0.f, 0.f, 0.f, 0.f);
    const float* base = g_Spart + (size_t)b * CO + c * ODIM + q * 4;
    #pragma unroll 4
    for (int gx = 0; gx < GX; gx++) {
        float4 p = *reinterpret_cast<const float4*>(base + (size_t)gx * BATCH * CO);
        s.x += p.x; s.y += p.y; s.z += p.z; s.w += p.w;
    }
    s.x *= mult; s.y *= mult; s.z *= mult; s.w *= mult;

    float n2 = s.x * s.x + s.y * s.y + s.z * s.z + s.w * s.w;
    n2 += __shfl_xor_sync(0xffffffffu, n2, 1);
    n2 += __shfl_xor_sync(0xffffffffu, n2, 2);
    float n = sqrtf(n2);
    float f = n2 / ((1.f + n2) * (n + 1e-8f));

    float* dst = g_vsum + b * CO + c * ODIM + q * 4;
    if (add_mode) {
        dst[0] += f * s.x; dst[1] += f * s.y; dst[2] += f * s.z; dst[3] += f * s.w;
    } else {
        dst[0] = f * s.x; dst[1] = f * s.y; dst[2] = f * s.z; dst[3] = f * s.w;
    }
}

// ---------------- final: sum partials, squash, lengths, argmax, vtop -------
// grid (BATCH), 256 threads (200 active for the sums). Proper shfl masks.
__global__ void final_kernel(float* __restrict__ out)
{
    __shared__ float v_s[NCAPS * ODIM];
    __shared__ float len_s[NCAPS];
    __shared__ int am_s;

    const int b = blockIdx.x, t = threadIdx.x;
    if (t < 200) {
        // warp 6 has only lanes 0-7 active here -> mask must match
        const unsigned mask = ((t >> 5) == 6) ? 0xffu : 0xffffffffu;
        int c = t >> 2, q = t & 3;
        float4 s = make_float4(0.f, 0.f, 0.f, 0.f);
        const float* base = g_Spart + (size_t)b * CO + c * ODIM + q * 4;
        #pragma unroll 4
        for (int gx = 0; gx < GX; gx++) {
            float4 p = *reinterpret_cast<const float4*>(base + (size_t)gx * BATCH * CO);
            s.x += p.x; s.y += p.y; s.z += p.z; s.w += p.w;
        }
        float n2 = s.x * s.x + s.y * s.y + s.z * s.z + s.w * s.w;
        n2 += __shfl_xor_sync(mask, n2, 1);
        n2 += __shfl_xor_sync(mask, n2, 2);
        float n = sqrtf(n2);
        float f = n2 / ((1.f + n2) * (n + 1e-8f));
        float* vd = v_s + c * ODIM + q * 4;
        vd[0] = f * s.x; vd[1] = f * s.y; vd[2] = f * s.z; vd[3] = f * s.w;
        if (q == 0) {
            float len = f * n;
            len_s[c] = len;
            out[b * NCAPS + c] = len;
        }
    }
    __syncthreads();
    if (t == 0) {
        int best = 0; float bl = len_s[0];
        for (int c = 1; c < NCAPS; c++) if (len_s[c] > bl) { bl = len_s[c]; best = c; }
        am_s = best;
        g_amax[b] = best;
    }
    __syncthreads();
    if (t < ODIM) g_vtop[b * ODIM + t] = v_s[am_s * ODIM + t];
}

// ---------------- MLP layer 1 (16-sparse input) ----------------------------
__global__ void mlp1_kernel(const float* __restrict__ w1, const float* __restrict__ b1)
{
    __shared__ float vt[ODIM];
    __shared__ int am;
    const int b = blockIdx.x, t = threadIdx.x;
    if (t < ODIM) vt[t] = g_vtop[b * ODIM + t];
    if (t == 0) am = g_amax[b];
    __syncthreads();
    float acc = b1[t];
    const int row0 = am * ODIM;
    #pragma unroll
    for (int o = 0; o < 16; o++) acc = fmaf(vt[o], w1[(row0 + o) * HID1 + t], acc);
    g_h1[b * HID1 + t] = acc > 0.f ? acc : 0.f;
}

// ---------------- MLP layer 2 ----------------------------------------------
__global__ __launch_bounds__(256) void mlp2_kernel(const float* __restrict__ w2,
                                                   const float* __restrict__ b2)
{
    __shared__ float h1s[8 * HID1];
    const int t = threadIdx.x;
    const int n = blockIdx.x * 256 + t;
    const int bb = blockIdx.y * 8;
    for (int f = t; f < 8 * HID1; f += 256) {
        int b8 = f >> 9, k = f & 511;
        h1s[f] = g_h1[(bb + b8) * HID1 + k];
    }
    __syncthreads();
    float acc[8];
    float bias = b2[n];
    #pragma unroll
    for (int b8 = 0; b8 < 8; b8++) acc[b8] = bias;
    #pragma unroll 4
    for (int k = 0; k < HID1; k++) {
        float w = w2[(size_t)k * HID2 + n];
        #pragma unroll
        for (int b8 = 0; b8 < 8; b8++) acc[b8] = fmaf(h1s[b8 * HID1 + k], w, acc[b8]);
    }
    #pragma unroll
    for (int b8 = 0; b8 < 8; b8++) {
        float v = acc[b8];
        g_h2[(bb + b8) * HID2 + n] = v > 0.f ? v : 0.f;
    }
}

// ---------------- MLP layer 3 + sigmoid -> recon ---------------------------
__global__ __launch_bounds__(128) void mlp3_kernel(const float* __restrict__ w3,
                                                   const float* __restrict__ b3,
                                                   float* __restrict__ recon)
{
    extern __shared__ float h2s[];
    const int t = threadIdx.x;
    const int n = blockIdx.x * 128 + t;
    const int bb = blockIdx.y * 16;
    for (int f = t; f < 16 * HID2; f += 128) {
        int b16 = f >> 10, k = f & 1023;
        h2s[f] = g_h2[(bb + b16) * HID2 + k];
    }
    __syncthreads();
    if (n >= NOUT) return;

    float acc[16];
    float bias = b3[n];
    #pragma unroll
    for (int b16 = 0; b16 < 16; b16++) acc[b16] = bias;

    for (int k0 = 0; k0 < HID2; k0 += 4) {
        float w0 = w3[(size_t)(k0 + 0) * NOUT + n];
        float w1v = w3[(size_t)(k0 + 1) * NOUT + n];
        float w2v = w3[(size_t)(k0 + 2) * NOUT + n];
        float w3v = w3[(size_t)(k0 + 3) * NOUT + n];
        #pragma unroll
        for (int b16 = 0; b16 < 16; b16++) {
            float4 h = *reinterpret_cast<const float4*>(&h2s[b16 * HID2 + k0]);
            float a = acc[b16];
            a = fmaf(h.x, w0, a);
            a = fmaf(h.y, w1v, a);
            a = fmaf(h.z, w2v, a);
            a = fmaf(h.w, w3v, a);
            acc[b16] = a;
        }
    }
    #pragma unroll
    for (int b16 = 0; b16 < 16; b16++) {
        float s = 1.f / (1.f + expf(-acc[b16]));
        recon[(size_t)(bb + b16) * NOUT + n] = s;
    }
}

// ---------------- launch ----------------------------------------------------
extern "C" void kernel_launch(void* const* d_in, const int* in_sizes, int n_in,
                              void* d_out, int out_size)
{
    const int*   x      = (const int*)  d_in[0];
    const float* emb    = (const float*)d_in[1];
    const float* conv_w = (const float*)d_in[2];
    const float* conv_b = (const float*)d_in[3];
    const float* W      = (const float*)d_in[4];
    const float* w1     = (const float*)d_in[5];
    const float* b1     = (const float*)d_in[6];
    const float* w2     = (const float*)d_in[7];
    const float* b2     = (const float*)d_in[8];
    const float* w3     = (const float*)d_in[9];
    const float* b3     = (const float*)d_in[10];
    float* out = (float*)d_out;
    float* recon = out + ((size_t)out_size - (size_t)BATCH * NOUT);

    const int route_smem = SMEM_FLOATS * (int)sizeof(float);   // ~168 KB

    static int attr_done = 0;
    if (!attr_done) {
        cudaFuncSetAttribute(mlp3_kernel, cudaFuncAttributeMaxDynamicSharedMemorySize,
                             16 * HID2 * sizeof(float));
        cudaFuncSetAttribute(route_kernel<0>, cudaFuncAttributeMaxDynamicSharedMemorySize,
                             route_smem);
        cudaFuncSetAttribute(route_kernel<1>, cudaFuncAttributeMaxDynamicSharedMemorySize,
                             route_smem);
        attr_done = 1;
    }

    // 1. conv/embed -> u   (4 l-tiles of 24 = LOUT 96)
    conv_embed_kernel<<<dim3(4, BATCH), 256>>>(x, emb, conv_w, conv_b);

    // 2. pass 0: S0 partials (uniform coefficients)
    route_kernel<0><<<dim3(GX, BATCH / BT), 256, route_smem>>>(W);

    // 3. v0 = squash(S0/50); vsum = v0
    squash_partials_kernel<<<(BATCH * NCAPS * 4) / 256, 256>>>(1.f / (float)NCAPS, 0);

    // 4. pass 1: s1 partials (softmax vs v0)
    route_kernel<1><<<dim3(GX, BATCH / BT), 256, route_smem>>>(W);

    // 5. v1 = squash(s1); vsum += v1
    squash_partials_kernel<<<(BATCH * NCAPS * 4) / 256, 256>>>(1.f, 1);

    // 6. pass 2: s2 partials (softmax vs v0+v1)
    route_kernel<1><<<dim3(GX, BATCH / BT), 256, route_smem>>>(W);

    // 7. final v, lengths, argmax, vtop
    final_kernel<<<BATCH, 256>>>(out);

    // 8. MLP + sigmoid
    mlp1_kernel<<<BATCH, HID1>>>(w1, b1);
    mlp2_kernel<<<dim3(HID2 / 256, BATCH / 8), 256>>>(w2, b2);
    mlp3_kernel<<<dim3((NOUT + 127) / 128, BATCH / 16), 128,
                 16 * HID2 * sizeof(float)>>>(w3, b3, recon);
}

// round 5
// speedup vs baseline: 2.7497x; 1.0502x over previous
#include <cuda_runtime.h>
#include <math.h>
#include <stdint.h>

// ---------------- problem constants ----------------
#define BATCH   64
#define SEQ     200
#define EMBED   64
#define VOCAB   95
#define LOUT    96
#define NCAPS   50
#define CAPSD   8
#define ODIM    16
#define NROUTE  3072
#define HID1    512
#define HID2    1024
#define NOUT    19000
#define CO      (NCAPS*ODIM)     // 800

// routing-recompute tiling
#define RT_PHASE 2                      // routes per smem tile
#define R_LOOP   16                     // routes per block
#define NPHASE   (R_LOOP/RT_PHASE)      // 8
#define GX       (NROUTE/R_LOOP)        // 192
#define BT       8                      // batches per block (2 quads x 4)
#define WROW     144                    // padded floats per c-row (16 mod 32 -> conflict-free)
#define WTILE    (RT_PHASE*NCAPS*WROW)  // 14400 floats per buffer
#define SMEM_FLOATS (2*WTILE)

// ---------------- device scratch ----------------
__device__ float g_u[BATCH * NROUTE * CAPSD];            // 6.3 MB
__device__ float g_Spart[(size_t)GX * BATCH * CO];       // 39.3 MB partial s
__device__ float g_vsum[BATCH * CO];
__device__ float g_h1[BATCH * HID1];
__device__ float g_h2[BATCH * HID2];

// ---------------- kernel 1: embedding + conv1d + relu -> u ----------------
// grid (4, BATCH): x = l-quarter (24 outputs each), y = b. 256 threads = channels.
#define SEROW 60
__global__ __launch_bounds__(256, 2) void conv_embed_kernel(
    const int* __restrict__ x, const float* __restrict__ emb,
    const float* __restrict__ cw, const float* __restrict__ cb)
{
    __shared__ int   xs[56];
    __shared__ float se_t[EMBED * SEROW];   // [ic][s], row stride 60 (float4-aligned)

    const int l0 = blockIdx.x * 24;
    const int b  = blockIdx.y;
    const int t  = threadIdx.x;

    if (t < 55) xs[t] = x[b * SEQ + 2 * l0 + t];
    __syncthreads();
    for (int f = t; f < 55 * EMBED; f += 256) {
        int s = f >> 6, ic = f & 63;
        se_t[ic * SEROW + s] = emb[xs[s] * EMBED + ic];
    }
    __syncthreads();

    const int ch = t;
    float acc[24];
    {
        float bias = cb[ch];
        #pragma unroll
        for (int j = 0; j < 24; j++) acc[j] = bias;
    }

    const float* cwr = cw + (size_t)ch * (EMBED * 9);
    for (int ic = 0; ic < EMBED; ic++) {
        float w_r[9];
        #pragma unroll
        for (int k = 0; k < 9; k++) w_r[k] = __ldg(cwr + ic * 9 + k);

        // full 56-float window in registers via 14 broadcast LDS.128
        float se_r[56];
        const float4* rowp = reinterpret_cast<const float4*>(se_t + ic * SEROW);
        #pragma unroll
        for (int q = 0; q < 14; q++) {
            float4 v = rowp[q];
            se_r[4*q] = v.x; se_r[4*q+1] = v.y; se_r[4*q+2] = v.z; se_r[4*q+3] = v.w;
        }

        #pragma unroll
        for (int j = 0; j < 24; j++) {
            float a = acc[j];
            #pragma unroll
            for (int k = 0; k < 9; k++) a = fmaf(se_r[2 * j + k], w_r[k], a);
            acc[j] = a;
        }
    }

    const int g = ch >> 3, i = ch & 7;
    #pragma unroll
    for (int j = 0; j < 24; j++) {
        int l = l0 + j;
        float v = acc[j];
        v = v > 0.f ? v : 0.f;
        g_u[((size_t)(b * NROUTE) + g * LOUT + l) * CAPSD + i] = v;
    }
}

// ---------------- routing by recompute (quad-warp) -------------------------
// MODE 0: coef uniform; MODE 1: coef = softmax_c(uhat.vsum)
// grid (GX, 8). 256 threads = 2 quads x 4 warps. Quad covers the 800-float
// row: lane128 = wq*32+lane; slot j in {0,1}: v = j*128+lane128, floats
// 4v..4v+3, c = v>>2, valid while v < 200. Each quad processes 4 batches.
template<int MODE>
__global__ __launch_bounds__(256) void route_kernel(const float* __restrict__ W)
{
    extern __shared__ float sm[];                 // 2 x WTILE
    __shared__ float su[BT][128];                 // u staged: [batch][route*8+i]
    __shared__ float redmax[2][4][4];             // [quad][wq][k]
    __shared__ float redsum[2][4][4];

    const int gx    = blockIdx.x;
    const int b0blk = blockIdx.y * BT;
    const int t     = threadIdx.x;
    const int warp  = t >> 5, lane = t & 31;
    const int q     = warp >> 2;                  // quad 0/1
    const int wq    = warp & 3;
    const int lane128 = wq * 32 + lane;
    const int rbase = gx * R_LOOP;

    // slot geometry
    const int v0 = lane128;                       // j=0: always valid (<128)
    const int v1 = 128 + lane128;
    const bool val1 = (v1 < 200);
    const int c0 = v0 >> 2;
    const int c1 = val1 ? (v1 >> 2) : 0;
    const int o40 = (v0 & 3) * 4;
    const int o41 = (v1 & 3) * 4;

    // stage u for this block's 8 batches x 16 routes (coalesced float4)
    {
        const float4* src;
        for (int idx = t; idx < BT * 32; idx += 256) {
            int bk = idx >> 5, f4 = idx & 31;
            src = reinterpret_cast<const float4*>(
                g_u + ((size_t)((b0blk + bk) * NROUTE + rbase)) * CAPSD);
            reinterpret_cast<float4*>(su[bk])[f4] = src[f4];
        }
    }

    // vsum in registers: fixed (b, v) per thread
    float4 vsA[4], vsB[4];
    if (MODE) {
        #pragma unroll
        for (int k = 0; k < 4; k++) {
            int b = b0blk + q * 4 + k;
            vsA[k] = *reinterpret_cast<const float4*>(g_vsum + b * CO + 4 * v0);
            vsB[k] = val1 ? *reinterpret_cast<const float4*>(g_vsum + b * CO + 4 * v1)
                          : make_float4(0.f, 0.f, 0.f, 0.f);
        }
    }

    float4 accA[4], accB[4];
    #pragma unroll
    for (int k = 0; k < 4; k++) {
        accA[k] = make_float4(0.f, 0.f, 0.f, 0.f);
        accB[k] = make_float4(0.f, 0.f, 0.f, 0.f);
    }

    // ---- prefetch tile 0
    {
        for (int idx = t; idx < RT_PHASE * NCAPS * 32; idx += 256) {
            int rl = idx / (NCAPS * 32);
            int rem = idx - rl * (NCAPS * 32);
            int c = rem >> 5, kk = rem & 31;
            const float* src = W + ((size_t)(c * NROUTE + rbase + rl)) * 128 + kk * 4;
            float* dst = sm + rl * (NCAPS * WROW) + c * WROW + kk * 4;
            uint32_t ds = (uint32_t)__cvta_generic_to_shared(dst);
            asm volatile("cp.async.ca.shared.global [%0], [%1], 16;\n" :: "r"(ds), "l"(src));
        }
        asm volatile("cp.async.commit_group;\n");
    }

    for (int p = 0; p < NPHASE; p++) {
        if (p + 1 < NPHASE) {
            float* dstbase = sm + ((p + 1) & 1) * WTILE;
            const int rp = rbase + (p + 1) * RT_PHASE;
            for (int idx = t; idx < RT_PHASE * NCAPS * 32; idx += 256) {
                int rl = idx / (NCAPS * 32);
                int rem = idx - rl * (NCAPS * 32);
                int c = rem >> 5, kk = rem & 31;
                const float* src = W + ((size_t)(c * NROUTE + rp + rl)) * 128 + kk * 4;
                float* dst = dstbase + rl * (NCAPS * WROW) + c * WROW + kk * 4;
                uint32_t ds = (uint32_t)__cvta_generic_to_shared(dst);
                asm volatile("cp.async.ca.shared.global [%0], [%1], 16;\n" :: "r"(ds), "l"(src));
            }
            asm volatile("cp.async.commit_group;\n");
            asm volatile("cp.async.wait_group 1;\n");
        } else {
            asm volatile("cp.async.wait_group 0;\n");
        }
        __syncthreads();

        const float* wbuf = sm + (p & 1) * WTILE;

        #pragma unroll
        for (int rl = 0; rl < RT_PHASE; rl++) {
            const int roff = p * RT_PHASE + rl;     // 0..15

            // u for 4 batches from smem (broadcast)
            float u[4][8];
            #pragma unroll
            for (int k = 0; k < 4; k++) {
                const float4* up = reinterpret_cast<const float4*>(&su[q * 4 + k][roff * 8]);
                float4 a = up[0], b2 = up[1];
                u[k][0]=a.x; u[k][1]=a.y; u[k][2]=a.z; u[k][3]=a.w;
                u[k][4]=b2.x; u[k][5]=b2.y; u[k][6]=b2.z; u[k][7]=b2.w;
            }

            const float* wr = wbuf + rl * (NCAPS * WROW);

            // slot 0 (always valid)
            float4 uhA[4];
            {
                const float* wc = wr + c0 * WROW + o40;
                #pragma unroll
                for (int k = 0; k < 4; k++) uhA[k] = make_float4(0.f,0.f,0.f,0.f);
                #pragma unroll
                for (int i = 0; i < 8; i++) {
                    float4 w4 = *reinterpret_cast<const float4*>(wc + i * 16);
                    #pragma unroll
                    for (int k = 0; k < 4; k++) {
                        uhA[k].x = fmaf(u[k][i], w4.x, uhA[k].x);
                        uhA[k].y = fmaf(u[k][i], w4.y, uhA[k].y);
                        uhA[k].z = fmaf(u[k][i], w4.z, uhA[k].z);
                        uhA[k].w = fmaf(u[k][i], w4.w, uhA[k].w);
                    }
                }
            }
            // slot 1 (partial validity; invalid lanes compute on c=0, discarded)
            float4 uhB[4];
            {
                const float* wc = wr + c1 * WROW + o41;
                #pragma unroll
                for (int k = 0; k < 4; k++) uhB[k] = make_float4(0.f,0.f,0.f,0.f);
                #pragma unroll
                for (int i = 0; i < 8; i++) {
                    float4 w4 = *reinterpret_cast<const float4*>(wc + i * 16);
                    #pragma unroll
                    for (int k = 0; k < 4; k++) {
                        uhB[k].x = fmaf(u[k][i], w4.x, uhB[k].x);
                        uhB[k].y = fmaf(u[k][i], w4.y, uhB[k].y);
                        uhB[k].z = fmaf(u[k][i], w4.z, uhB[k].z);
                        uhB[k].w = fmaf(u[k][i], w4.w, uhB[k].w);
                    }
                }
            }

            if (MODE) {
                float dA[4], dB[4];
                #pragma unroll
                for (int k = 0; k < 4; k++) {
                    float da = uhA[k].x * vsA[k].x;
                    da = fmaf(uhA[k].y, vsA[k].y, da);
                    da = fmaf(uhA[k].z, vsA[k].z, da);
                    da = fmaf(uhA[k].w, vsA[k].w, da);
                    float db = uhB[k].x * vsB[k].x;
                    db = fmaf(uhB[k].y, vsB[k].y, db);
                    db = fmaf(uhB[k].z, vsB[k].z, db);
                    db = fmaf(uhB[k].w, vsB[k].w, db);
                    da += __shfl_xor_sync(0xffffffffu, da, 1);
                    da += __shfl_xor_sync(0xffffffffu, da, 2);
                    db += __shfl_xor_sync(0xffffffffu, db, 1);
                    db += __shfl_xor_sync(0xffffffffu, db, 2);
                    dA[k] = da;
                    dB[k] = val1 ? db : -1e30f;
                }
                // warp-local max
                float mt[4];
                #pragma unroll
                for (int k = 0; k < 4; k++) {
                    float m = fmaxf(dA[k], dB[k]);
                    #pragma unroll
                    for (int off = 16; off >= 1; off >>= 1)
                        m = fmaxf(m, __shfl_xor_sync(0xffffffffu, m, off));
                    mt[k] = m;
                }
                if (lane == 0) {
                    #pragma unroll
                    for (int k = 0; k < 4; k++) redmax[q][wq][k] = mt[k];
                }
                asm volatile("bar.sync %0, 128;" :: "r"(1 + q) : "memory");
                float gmax[4];
                #pragma unroll
                for (int k = 0; k < 4; k++)
                    gmax[k] = fmaxf(fmaxf(redmax[q][0][k], redmax[q][1][k]),
                                    fmaxf(redmax[q][2][k], redmax[q][3][k]));
                // exp + warp-local sum
                float eA[4], eB[4], zt[4];
                #pragma unroll
                for (int k = 0; k < 4; k++) {
                    eA[k] = __expf(dA[k] - gmax[k]);
                    eB[k] = val1 ? __expf(dB[k] - gmax[k]) : 0.f;
                    float z = eA[k] + eB[k];
                    #pragma unroll
                    for (int off = 16; off >= 1; off >>= 1)
                        z += __shfl_xor_sync(0xffffffffu, z, off);
                    zt[k] = z;
                }
                if (lane == 0) {
                    #pragma unroll
                    for (int k = 0; k < 4; k++) redsum[q][wq][k] = zt[k];
                }
                asm volatile("bar.sync %0, 128;" :: "r"(1 + q) : "memory");
                #pragma unroll
                for (int k = 0; k < 4; k++) {
                    // each c counted on 4 lanes -> Z = sum/4
                    float Z = (redsum[q][0][k] + redsum[q][1][k] +
                               redsum[q][2][k] + redsum[q][3][k]) * 0.25f;
                    float inv = 1.f / Z;
                    float cfA = eA[k] * inv;
                    float cfB = eB[k] * inv;
                    accA[k].x = fmaf(cfA, uhA[k].x, accA[k].x);
                    accA[k].y = fmaf(cfA, uhA[k].y, accA[k].y);
                    accA[k].z = fmaf(cfA, uhA[k].z, accA[k].z);
                    accA[k].w = fmaf(cfA, uhA[k].w, accA[k].w);
                    accB[k].x = fmaf(cfB, uhB[k].x, accB[k].x);
                    accB[k].y = fmaf(cfB, uhB[k].y, accB[k].y);
                    accB[k].z = fmaf(cfB, uhB[k].z, accB[k].z);
                    accB[k].w = fmaf(cfB, uhB[k].w, accB[k].w);
                }
            } else {
                #pragma unroll
                for (int k = 0; k < 4; k++) {
                    accA[k].x += uhA[k].x; accA[k].y += uhA[k].y;
                    accA[k].z += uhA[k].z; accA[k].w += uhA[k].w;
                    accB[k].x += uhB[k].x; accB[k].y += uhB[k].y;
                    accB[k].z += uhB[k].z; accB[k].w += uhB[k].w;
                }
            }
        }
        __syncthreads();
    }

    // write partial s (coalesced float4, no atomics)
    #pragma unroll
    for (int k = 0; k < 4; k++) {
        int b = b0blk + q * 4 + k;
        float* pb = g_Spart + ((size_t)gx * BATCH + b) * CO;
        *reinterpret_cast<float4*>(pb + 4 * v0) = accA[k];
        if (val1) *reinterpret_cast<float4*>(pb + 4 * v1) = accB[k];
    }
}

// ---------------- squash over partials -------------------------------------
// vsum = (add? vsum : 0) + squash(sum_gx(Spart) * mult). 12800 threads exact.
__global__ __launch_bounds__(256) void squash_partials_kernel(float mult, int add_mode)
{
    int idx = blockIdx.x * blockDim.x + threadIdx.x;
    int q = idx & 3, bc = idx >> 2;
    int b = bc / NCAPS, c = bc - b * NCAPS;

    float4 s = make_float4(0.f, 0.f, 0.f, 0.f);
    const float* base = g_Spart + (size_t)b * CO + c * ODIM + q * 4;
    #pragma unroll 4
    for (int gx = 0; gx < GX; gx++) {
        float4 p = *reinterpret_cast<const float4*>(base + (size_t)gx * BATCH * CO);
        s.x += p.x; s.y += p.y; s.z += p.z; s.w += p.w;
    }
    s.x *= mult; s.y *= mult; s.z *= mult; s.w *= mult;

    float n2 = s.x * s.x + s.y * s.y + s.z * s.z + s.w * s.w;
    n2 += __shfl_xor_sync(0xffffffffu, n2, 1);
    n2 += __shfl_xor_sync(0xffffffffu, n2, 2);
    float n = sqrtf(n2);
    float f = n2 / ((1.f + n2) * (n + 1e-8f));

    float* dst = g_vsum + b * CO + c * ODIM + q * 4;
    if (add_mode) {
        dst[0] += f * s.x; dst[1] += f * s.y; dst[2] += f * s.z; dst[3] += f * s.w;
    } else {
        dst[0] = f * s.x; dst[1] = f * s.y; dst[2] = f * s.z; dst[3] = f * s.w;
    }
}

// ---------------- final: squash(s2), lengths, argmax + fused MLP layer 1 ---
// grid (BATCH), 256 threads.
__global__ void final_kernel(float* __restrict__ out,
                             const float* __restrict__ w1, const float* __restrict__ b1)
{
    __shared__ float v_s[NCAPS * ODIM];
    __shared__ float len_s[NCAPS];
    __shared__ int am_s;

    const int b = blockIdx.x, t = threadIdx.x;
    if (t < 200) {
        const unsigned mask = ((t >> 5) == 6) ? 0xffu : 0xffffffffu;
        int c = t >> 2, q = t & 3;
        float4 s = make_float4(0.f, 0.f, 0.f, 0.f);
        const float* base = g_Spart + (size_t)b * CO + c * ODIM + q * 4;
        #pragma unroll 4
        for (int gx = 0; gx < GX; gx++) {
            float4 p = *reinterpret_cast<const float4*>(base + (size_t)gx * BATCH * CO);
            s.x += p.x; s.y += p.y; s.z += p.z; s.w += p.w;
        }
        float n2 = s.x * s.x + s.y * s.y + s.z * s.z + s.w * s.w;
        n2 += __shfl_xor_sync(mask, n2, 1);
        n2 += __shfl_xor_sync(mask, n2, 2);
        float n = sqrtf(n2);
        float f = n2 / ((1.f + n2) * (n + 1e-8f));
        float* vd = v_s + c * ODIM + q * 4;
        vd[0] = f * s.x; vd[1] = f * s.y; vd[2] = f * s.z; vd[3] = f * s.w;
        if (q == 0) {
            float len = f * n;
            len_s[c] = len;
            out[b * NCAPS + c] = len;
        }
    }
    __syncthreads();
    if (t == 0) {
        int best = 0; float bl = len_s[0];
        for (int c = 1; c < NCAPS; c++) if (len_s[c] > bl) { bl = len_s[c]; best = c; }
        am_s = best;
    }
    __syncthreads();

    // fused MLP layer 1: h1[n] = relu(b1[n] + sum_o vtop[o]*w1[(am*16+o)*512+n])
    const int row0 = am_s * ODIM;
    #pragma unroll
    for (int h = 0; h < 2; h++) {
        int n = h * 256 + t;
        float acc = b1[n];
        #pragma unroll
        for (int o = 0; o < 16; o++)
            acc = fmaf(v_s[row0 + o], w1[(row0 + o) * HID1 + n], acc);
        g_h1[b * HID1 + n] = acc > 0.f ? acc : 0.f;
    }
}

// ---------------- MLP layer 2 ----------------------------------------------
__global__ __launch_bounds__(256) void mlp2_kernel(const float* __restrict__ w2,
                                                   const float* __restrict__ b2)
{
    __shared__ float h1s[8 * HID1];
    const int t = threadIdx.x;
    const int n = blockIdx.x * 256 + t;
    const int bb = blockIdx.y * 8;
    for (int f = t; f < 8 * HID1; f += 256) {
        int b8 = f >> 9, k = f & 511;
        h1s[f] = g_h1[(bb + b8) * HID1 + k];
    }
    __syncthreads();
    float acc[8];
    float bias = b2[n];
    #pragma unroll
    for (int b8 = 0; b8 < 8; b8++) acc[b8] = bias;
    #pragma unroll 4
    for (int k = 0; k < HID1; k++) {
        float w = w2[(size_t)k * HID2 + n];
        #pragma unroll
        for (int b8 = 0; b8 < 8; b8++) acc[b8] = fmaf(h1s[b8 * HID1 + k], w, acc[b8]);
    }
    #pragma unroll
    for (int b8 = 0; b8 < 8; b8++) {
        float v = acc[b8];
        g_h2[(bb + b8) * HID2 + n] = v > 0.f ? v : 0.f;
    }
}

// ---------------- MLP layer 3 + sigmoid -> recon ---------------------------
// grid (75, 4), 256 threads, 64 KB dyn smem.
__global__ __launch_bounds__(256) void mlp3_kernel(const float* __restrict__ w3,
                                                   const float* __restrict__ b3,
                                                   float* __restrict__ recon)
{
    extern __shared__ float h2s[];   // [16][1024]
    const int t = threadIdx.x;
    const int n = blockIdx.x * 256 + t;
    const int bb = blockIdx.y * 16;
    {
        const float4* src = reinterpret_cast<const float4*>(g_h2 + bb * HID2);
        float4* dst = reinterpret_cast<float4*>(h2s);
        for (int f = t; f < 16 * HID2 / 4; f += 256) dst[f] = src[f];
    }
    __syncthreads();
    if (n >= NOUT) return;

    float acc[16];
    float bias = b3[n];
    #pragma unroll
    for (int b16 = 0; b16 < 16; b16++) acc[b16] = bias;

    for (int k0 = 0; k0 < HID2; k0 += 4) {
        float w0 = w3[(size_t)(k0 + 0) * NOUT + n];
        float w1v = w3[(size_t)(k0 + 1) * NOUT + n];
        float w2v = w3[(size_t)(k0 + 2) * NOUT + n];
        float w3v = w3[(size_t)(k0 + 3) * NOUT + n];
        #pragma unroll
        for (int b16 = 0; b16 < 16; b16++) {
            float4 h = *reinterpret_cast<const float4*>(&h2s[b16 * HID2 + k0]);
            float a = acc[b16];
            a = fmaf(h.x, w0, a);
            a = fmaf(h.y, w1v, a);
            a = fmaf(h.z, w2v, a);
            a = fmaf(h.w, w3v, a);
            acc[b16] = a;
        }
    }
    #pragma unroll
    for (int b16 = 0; b16 < 16; b16++) {
        float s = 1.f / (1.f + expf(-acc[b16]));
        recon[(size_t)(bb + b16) * NOUT + n] = s;
    }
}

// ---------------- launch ----------------------------------------------------
extern "C" void kernel_launch(void* const* d_in, const int* in_sizes, int n_in,
                              void* d_out, int out_size)
{
    const int*   x      = (const int*)  d_in[0];
    const float* emb    = (const float*)d_in[1];
    const float* conv_w = (const float*)d_in[2];
    const float* conv_b = (const float*)d_in[3];
    const float* W      = (const float*)d_in[4];
    const float* w1     = (const float*)d_in[5];
    const float* b1     = (const float*)d_in[6];
    const float* w2     = (const float*)d_in[7];
    const float* b2     = (const float*)d_in[8];
    const float* w3     = (const float*)d_in[9];
    const float* b3     = (const float*)d_in[10];
    float* out = (float*)d_out;
    float* recon = out + ((size_t)out_size - (size_t)BATCH * NOUT);

    const int route_smem = SMEM_FLOATS * (int)sizeof(float);   // 115.2 KB

    static int attr_done = 0;
    if (!attr_done) {
        cudaFuncSetAttribute(mlp3_kernel, cudaFuncAttributeMaxDynamicSharedMemorySize,
                             16 * HID2 * sizeof(float));
        cudaFuncSetAttribute(route_kernel<0>, cudaFuncAttributeMaxDynamicSharedMemorySize,
                             route_smem);
        cudaFuncSetAttribute(route_kernel<1>, cudaFuncAttributeMaxDynamicSharedMemorySize,
                             route_smem);
        attr_done = 1;
    }

    // 1. conv/embed -> u
    conv_embed_kernel<<<dim3(4, BATCH), 256>>>(x, emb, conv_w, conv_b);

    // 2. pass 0: S0 partials (uniform coefficients)
    route_kernel<0><<<dim3(GX, BATCH / BT), 256, route_smem>>>(W);

    // 3. v0 = squash(S0/50); vsum = v0
    squash_partials_kernel<<<(BATCH * NCAPS * 4) / 256, 256>>>(1.f / (float)NCAPS, 0);

    // 4. pass 1: s1 partials (softmax vs v0)
    route_kernel<1><<<dim3(GX, BATCH / BT), 256, route_smem>>>(W);

    // 5. v1 = squash(s1); vsum += v1
    squash_partials_kernel<<<(BATCH * NCAPS * 4) / 256, 256>>>(1.f, 1);

    // 6. pass 2: s2 partials (softmax vs v0+v1)
    route_kernel<1><<<dim3(GX, BATCH / BT), 256, route_smem>>>(W);

    // 7. final v, lengths, argmax + MLP layer 1
    final_kernel<<<BATCH, 256>>>(out, w1, b1);

    // 8. MLP layers 2,3 + sigmoid
    mlp2_kernel<<<dim3(HID2 / 256, BATCH / 8), 256>>>(w2, b2);
    mlp3_kernel<<<dim3((NOUT + 255) / 256, BATCH / 16), 256,
                 16 * HID2 * sizeof(float)>>>(w3, b3, recon);
}